// round 10
// baseline (speedup 1.0000x reference)
#include <cuda_runtime.h>

#define NB     64
#define NPER   2048
#define NTOT   131072          // NB*NPER
#define EE     1048576
#define KSEL   1639
#define PTOT   104896          // NB*KSEL
#define RANK_ASC 209715        // EE-1 - int(0.8*(EE-1))

// output layout (float32, concatenated in reference return order)
#define O1 6713344             // PTOT*64
#define O2 8810496             // O1 + 2*EE
#define O3 17199104            // O2 + EE*8
#define O4 17304000            // O3 + PTOT

#define NBKT  1024             // node buckets of 128 rows (32KB of x rows each)
#define BSH   7                // bucket = r >> 7

__device__ int      g_perm[PTOT];
__device__ int      g_newidx[NTOT];
__device__ unsigned g_Su[EE];            // order-preserving uint key of S
__device__ unsigned g_h1[65536];
__device__ unsigned g_h2[65536];
__device__ unsigned g_psum[64];
__device__ unsigned g_bh[NBKT];          // bucket histogram (self-zeroed by k_bscan)
__device__ int      g_boff[NBKT + 1];
__device__ unsigned g_bcur[NBKT];
__device__ int4     g_esort[EE];         // (r, c, eid, 0) sorted by bucket
__device__ unsigned g_binT;
__device__ unsigned g_rank2;
__device__ unsigned g_uth;

__device__ __forceinline__ unsigned f2u(float f) {
    unsigned u = __float_as_uint(f);
    return (u & 0x80000000u) ? ~u : (u | 0x80000000u);
}

// #1: bucket histogram over r endpoints (g_bh zeroed at load / by prior k_bscan).
__global__ void k_ehist(const int* __restrict__ ei) {
    int e = blockIdx.x * blockDim.x + threadIdx.x;
    atomicAdd(&g_bh[((unsigned)ei[e]) >> BSH], 1u);
}

// #2: one block, shuffle scan of 1024 bucket counts -> offsets; self-zero g_bh.
__global__ void k_bscan() {
    __shared__ unsigned warpsum[32];
    int t = threadIdx.x;
    unsigned h = g_bh[t];
    unsigned inc = h;
#pragma unroll
    for (int o = 1; o < 32; o <<= 1) {
        unsigned n = __shfl_up_sync(0xFFFFFFFFu, inc, o);
        if ((t & 31) >= o) inc += n;
    }
    if ((t & 31) == 31) warpsum[t >> 5] = inc;
    __syncthreads();
    if (t < 32) {
        unsigned w = warpsum[t];
#pragma unroll
        for (int o = 1; o < 32; o <<= 1) {
            unsigned n = __shfl_up_sync(0xFFFFFFFFu, w, o);
            if (t >= o) w += n;
        }
        warpsum[t] = w;
    }
    __syncthreads();
    unsigned incl = inc + ((t >= 32) ? warpsum[(t >> 5) - 1] : 0u);
    unsigned excl = incl - h;
    g_boff[t] = (int)excl;
    g_bcur[t] = excl;
    if (t == NBKT - 1) g_boff[NBKT] = (int)(excl + h);
    g_bh[t] = 0;                      // reset for next replay
}

// #3: scatter edges into bucket-sorted order (16B records; order within a
// bucket is nondeterministic but results are keyed by eid -> deterministic).
__global__ void k_escatter(const int* __restrict__ ei) {
    int e = blockIdx.x * blockDim.x + threadIdx.x;
    int r = ei[e], c = ei[EE + e];
    unsigned pos = atomicAdd(&g_bcur[((unsigned)r) >> BSH], 1u);
    g_esort[pos] = make_int4(r, c, e, 0);
}

// #4: S kernel, bucket-per-block. r rows live in L1 (32KB working set, ~8x
// reuse); c rows via __ldcg (L2 only, no L1 pollution). Per-edge math is
// bit-identical to prior rounds: same 16-lane float4 diff + XOR tree + expf.
__global__ void __launch_bounds__(512) k_S2(const float4* __restrict__ xv) {
    int b = blockIdx.x;
    int beg = g_boff[b], end = g_boff[b + 1];
    int t = threadIdx.x, lane = t & 15, g = t >> 4;   // 32 groups of 16 lanes
    for (int i = beg + g; i < end; i += 32) {
        int4 ed = g_esort[i];                          // broadcast 16B load
        float4 a = xv[(size_t)ed.x * 16 + lane];       // L1-cached (bucket rows)
        float4 bb = __ldcg(&xv[(size_t)ed.y * 16 + lane]);  // L2-only
        float dx = a.x - bb.x, dy = a.y - bb.y, dz = a.z - bb.z, dw = a.w - bb.w;
        float sq = dx * dx + dy * dy + dz * dz + dw * dw;
#pragma unroll
        for (int o = 8; o; o >>= 1) sq += __shfl_xor_sync(0xFFFFFFFFu, sq, o, 16);
        if (lane == 0) {
            float S = expf(sqrtf(sq));   // sq==0 -> S=1 (matches _safe_norm)
            unsigned u = f2u(S);
            g_Su[ed.z] = u;
            atomicAdd(&g_h1[u >> 16], 1u);
        }
    }
}

// #5: per-graph bitonic sort of (score desc, idx asc); writes perm + new_idx.
__global__ void k_topk(const float* __restrict__ score) {
    __shared__ unsigned long long keys[NPER];
    int b = blockIdx.x, t = threadIdx.x;
    for (int i = t; i < NPER; i += blockDim.x) {
        unsigned su = f2u(score[b * NPER + i]);
        keys[i] = (((unsigned long long)(~su)) << 32) | (unsigned)i;
    }
    __syncthreads();
    for (int k = 2; k <= NPER; k <<= 1) {
        for (int j = k >> 1; j > 0; j >>= 1) {
            for (int i = t; i < NPER; i += blockDim.x) {
                int ixj = i ^ j;
                if (ixj > i) {
                    unsigned long long a = keys[i], c = keys[ixj];
                    bool up = ((i & k) == 0);
                    if ((a > c) == up) { keys[i] = c; keys[ixj] = a; }
                }
            }
            __syncthreads();
        }
    }
    for (int i = t; i < NPER; i += blockDim.x) {
        int local = (int)(keys[i] & 0xFFFFFFFFull);
        int node  = b * NPER + local;
        if (i < KSEL) {
            int p = b * KSEL + i;
            g_perm[p] = node;
            g_newidx[node] = p;
        } else {
            g_newidx[node] = -1;
        }
    }
}

// Parallel partial sums: 64 blocks x 256 threads, each thread 4 bins (uint4).
__global__ void k_sum(int pass) {
    const uint4* hist4 = (const uint4*)(pass ? g_h2 : g_h1);
    __shared__ unsigned sh[8];
    int t = threadIdx.x;
    uint4 v = hist4[blockIdx.x * 256 + t];
    unsigned s = v.x + v.y + v.z + v.w;
#pragma unroll
    for (int o = 16; o; o >>= 1) s += __shfl_xor_sync(0xFFFFFFFFu, s, o);
    if ((t & 31) == 0) sh[t >> 5] = s;
    __syncthreads();
    if (t < 8) {
        s = sh[t];
#pragma unroll
        for (int o = 4; o; o >>= 1) s += __shfl_xor_sync(0xFFu, s, o, 8);
        if (t == 0) g_psum[blockIdx.x] = s;
    }
}

// One block: psums staged via SMEM, then 1024 threads shuffle-scan the
// winning 1024-bin chunk.
__global__ void k_find(int pass) {
    __shared__ unsigned warpsum[32];
    __shared__ unsigned spsum[64];
    __shared__ unsigned s_excl;
    __shared__ int s_blk;
    const unsigned* hist = pass ? g_h2 : g_h1;
    int t = threadIdx.x;
    unsigned target = pass ? g_rank2 : (unsigned)RANK_ASC;
    if (t < 64) spsum[t] = g_psum[t];
    __syncthreads();
    if (t == 0) {
        unsigned cum = 0;
        int B = 0;
        for (int i = 0; i < 64; i++) {
            unsigned p = spsum[i];
            if (target < cum + p) { B = i; break; }
            cum += p;
        }
        s_excl = cum; s_blk = B;
    }
    __syncthreads();
    int B = s_blk;
    unsigned h = hist[B * 1024 + t];
    unsigned inc = h;
#pragma unroll
    for (int o = 1; o < 32; o <<= 1) {
        unsigned n = __shfl_up_sync(0xFFFFFFFFu, inc, o);
        if ((t & 31) >= o) inc += n;
    }
    if ((t & 31) == 31) warpsum[t >> 5] = inc;
    __syncthreads();
    if (t < 32) {
        unsigned w = warpsum[t];
#pragma unroll
        for (int o = 1; o < 32; o <<= 1) {
            unsigned n = __shfl_up_sync(0xFFFFFFFFu, w, o);
            if (t >= o) w += n;
        }
        warpsum[t] = w;
    }
    __syncthreads();
    unsigned incl = inc + ((t >= 32) ? warpsum[(t >> 5) - 1] : 0u);
    unsigned excl = s_excl + incl - h;
    if (target >= excl && target < excl + h) {
        unsigned bin = (unsigned)(B * 1024 + t);
        if (pass == 0) { g_binT = bin; g_rank2 = target - excl; }
        else           { g_uth = (g_binT << 16) | bin; }
    }
}

// Pass-2 histogram; blocks 0-63 also re-zero g_h1 for the next replay.
__global__ void k_hist2() {
    int e = blockIdx.x * blockDim.x + threadIdx.x;
    if (e < 16384) ((uint4*)g_h1)[e] = make_uint4(0, 0, 0, 0);
    unsigned u = g_Su[e];
    if ((u >> 16) == g_binT) atomicAdd(&g_h2[u & 0xFFFFu], 1u);
}

// Streaming edge outputs: 2 threads/edge (indices, masked attrs, select).
// Threads 0..16383 also re-zero g_h2 for the next replay.
__global__ void k_edges(const int* __restrict__ ei, const float4* __restrict__ attr4,
                        float* __restrict__ out) {
    int h = blockIdx.x * blockDim.x + threadIdx.x;   // EE*2 threads
    if (h < 16384) ((uint4*)g_h2)[h] = make_uint4(0, 0, 0, 0);
    int e = h >> 1, half = h & 1;
    int r = ei[e], c = ei[EE + e];
    int nr = g_newidx[r], nc = g_newidx[c];
    bool valid = (nr >= 0) && (nc >= 0);
    if (half == 0) {
        out[O1 + e] = valid ? (float)nr : -1.0f;
    } else {
        out[O1 + EE + e] = valid ? (float)nc : -1.0f;
        out[O4 + e] = (g_Su[e] > g_uth) ? 1.0f : 0.0f;
    }
    float4 av = valid ? attr4[e * 2 + half] : make_float4(0, 0, 0, 0);
    ((float4*)(out + O2))[e * 2 + half] = av;
}

// x_out gather (16 threads/row, exact fp32) + batch_out.
__global__ void k_final(const float4* __restrict__ xv, float* __restrict__ out) {
    int t = blockIdx.x * blockDim.x + threadIdx.x;
    if (t < PTOT) out[O3 + t] = (float)(t / KSEL);
    if (t < PTOT * 16) {
        int p = t >> 4, j = t & 15;
        int node = g_perm[p];
        ((float4*)out)[p * 16 + j] = xv[(size_t)node * 16 + j];
    }
}

extern "C" void kernel_launch(void* const* d_in, const int* in_sizes, int n_in,
                              void* d_out, int out_size) {
    const float* x    = (const float*)d_in[0];
    const float* xs   = (const float*)d_in[1];
    const int*   ei   = (const int*)d_in[2];
    const float* attr = (const float*)d_in[3];
    float* out = (float*)d_out;

    k_ehist<<<EE / 256, 256>>>(ei);                // #1
    k_bscan<<<1, 1024>>>();                        // #2
    k_escatter<<<EE / 256, 256>>>(ei);             // #3
    k_S2<<<NBKT, 512>>>((const float4*)x);         // #4 (ncu capture slot)
    k_topk<<<NB, 1024>>>(xs);                      // #5
    k_sum<<<64, 256>>>(0);                         // #6
    k_find<<<1, 1024>>>(0);                        // #7
    k_hist2<<<EE / 256, 256>>>();                  // #8
    k_sum<<<64, 256>>>(1);                         // #9
    k_find<<<1, 1024>>>(1);                        // #10
    k_edges<<<EE * 2 / 256, 256>>>(ei, (const float4*)attr, out);  // #11
    k_final<<<PTOT * 16 / 256, 256>>>((const float4*)x, out);      // #12
}

// round 11
// speedup vs baseline: 1.3961x; 1.3961x over previous
#include <cuda_runtime.h>

#define NB     64
#define NPER   2048
#define NTOT   131072          // NB*NPER
#define EE     1048576
#define KSEL   1639
#define PTOT   104896          // NB*KSEL
#define RANK_ASC 209715        // EE-1 - int(0.8*(EE-1))

// output layout (float32, concatenated in reference return order)
#define O1 6713344             // PTOT*64
#define O2 8810496             // O1 + 2*EE
#define O3 17199104            // O2 + EE*8
#define O4 17304000            // O3 + PTOT

#define NBKT  1024             // node buckets of 128 rows (32KB of x rows each)
#define BSH   7                // bucket = r >> 7
#define EPB   4096             // edges per sort block (EE/256)

__device__ int      g_perm[PTOT];
__device__ int      g_newidx[NTOT];
__device__ unsigned g_Su[EE];            // order-preserving uint key of S
__device__ unsigned g_h1[65536];
__device__ unsigned g_h2[65536];
__device__ unsigned g_psum[64];
__device__ unsigned g_bh[NBKT];          // bucket histogram (self-zeroed by k_bscan)
__device__ int      g_boff[NBKT + 1];
__device__ unsigned g_bcur[NBKT];
__device__ int4     g_esort[EE];         // (r, c, eid, 0) bucket-sorted
__device__ unsigned g_binT;
__device__ unsigned g_rank2;
__device__ unsigned g_uth;

__device__ __forceinline__ unsigned f2u(float f) {
    unsigned u = __float_as_uint(f);
    return (u & 0x80000000u) ? ~u : (u | 0x80000000u);
}

// #1: bucket histogram via SMEM (low-contention), 256 blocks x 4096 edges.
__global__ void k_ehist(const int* __restrict__ ei) {
    __shared__ unsigned sh[NBKT];
    int t = threadIdx.x;
    for (int i = t; i < NBKT; i += 256) sh[i] = 0;
    __syncthreads();
    int base = blockIdx.x * EPB;
#pragma unroll 4
    for (int i = 0; i < 16; i++)
        atomicAdd(&sh[((unsigned)ei[base + i * 256 + t]) >> BSH], 1u);
    __syncthreads();
    for (int i = t; i < NBKT; i += 256) {
        unsigned v = sh[i];
        if (v) atomicAdd(&g_bh[i], v);
    }
}

// #2: one block, shuffle scan of 1024 bucket counts -> offsets; self-zero g_bh.
__global__ void k_bscan() {
    __shared__ unsigned warpsum[32];
    int t = threadIdx.x;
    unsigned h = g_bh[t];
    unsigned inc = h;
#pragma unroll
    for (int o = 1; o < 32; o <<= 1) {
        unsigned n = __shfl_up_sync(0xFFFFFFFFu, inc, o);
        if ((t & 31) >= o) inc += n;
    }
    if ((t & 31) == 31) warpsum[t >> 5] = inc;
    __syncthreads();
    if (t < 32) {
        unsigned w = warpsum[t];
#pragma unroll
        for (int o = 1; o < 32; o <<= 1) {
            unsigned n = __shfl_up_sync(0xFFFFFFFFu, w, o);
            if (t >= o) w += n;
        }
        warpsum[t] = w;
    }
    __syncthreads();
    unsigned incl = inc + ((t >= 32) ? warpsum[(t >> 5) - 1] : 0u);
    unsigned excl = incl - h;
    g_boff[t] = (int)excl;
    g_bcur[t] = excl;
    if (t == NBKT - 1) g_boff[NBKT] = (int)(excl + h);
    g_bh[t] = 0;                      // reset for next replay
}

// #3: scatter via per-block SMEM hist + one range-reservation atomic per
// (block,bucket). Global atomic contention <= 256 per address.
__global__ void k_escatter(const int* __restrict__ ei) {
    __shared__ unsigned lh[NBKT];     // local counts, then local cursors
    __shared__ unsigned lbase[NBKT];
    int t = threadIdx.x;
    for (int i = t; i < NBKT; i += 256) lh[i] = 0;
    __syncthreads();
    int base = blockIdx.x * EPB;
#pragma unroll 4
    for (int i = 0; i < 16; i++)
        atomicAdd(&lh[((unsigned)ei[base + i * 256 + t]) >> BSH], 1u);
    __syncthreads();
    for (int i = t; i < NBKT; i += 256) {
        unsigned cnt = lh[i];
        lbase[i] = cnt ? atomicAdd(&g_bcur[i], cnt) : 0u;
        lh[i] = 0;                    // reuse as local cursor
    }
    __syncthreads();
#pragma unroll 4
    for (int i = 0; i < 16; i++) {
        int e = base + i * 256 + t;
        int r = ei[e], c = ei[EE + e];
        unsigned bkt = ((unsigned)r) >> BSH;
        unsigned pos = lbase[bkt] + atomicAdd(&lh[bkt], 1u);
        g_esort[pos] = make_int4(r, c, e, 0);
    }
}

// #4: S kernel, bucket-per-block with r-rows staged in SMEM (32KB, guaranteed
// hits, zero L1tex miss slots). Only c-rows miss -> ~2.25M lines vs 4M.
// Per-edge math bit-identical: same lane/float4 mapping, XOR tree, expf.
__global__ void __launch_bounds__(256) k_S2(const float4* __restrict__ xv) {
    __shared__ float4 s_x[128 * 16];   // 32 KB: this bucket's 128 rows
    int b = blockIdx.x, t = threadIdx.x;
    for (int i = t; i < 2048; i += 256)
        s_x[i] = xv[(size_t)b * 2048 + i];
    int beg = g_boff[b], end = g_boff[b + 1];
    __syncthreads();
    int lane = t & 15, g = t >> 4;     // 16 groups of 16 lanes
    if (beg + g >= end) return;
    int4 ed = g_esort[beg + g];
    for (int i = beg + g; i < end; i += 16) {
        int inext = i + 16;
        int4 ednext = (inext < end) ? g_esort[inext] : ed;   // prefetch
        float4 a  = s_x[(((unsigned)ed.x) & 127u) * 16 + lane];
        float4 bb = __ldg(&xv[(size_t)ed.y * 16 + lane]);
        float dx = a.x - bb.x, dy = a.y - bb.y, dz = a.z - bb.z, dw = a.w - bb.w;
        float sq = dx * dx + dy * dy + dz * dz + dw * dw;
#pragma unroll
        for (int o = 8; o; o >>= 1) sq += __shfl_xor_sync(0xFFFFFFFFu, sq, o, 16);
        if (lane == 0) {
            float S = expf(sqrtf(sq));   // sq==0 -> S=1 (matches _safe_norm)
            unsigned u = f2u(S);
            g_Su[ed.z] = u;
            atomicAdd(&g_h1[u >> 16], 1u);
        }
        ed = ednext;
    }
}

// #5: per-graph bitonic sort of (score desc, idx asc); writes perm + new_idx.
__global__ void k_topk(const float* __restrict__ score) {
    __shared__ unsigned long long keys[NPER];
    int b = blockIdx.x, t = threadIdx.x;
    for (int i = t; i < NPER; i += blockDim.x) {
        unsigned su = f2u(score[b * NPER + i]);
        keys[i] = (((unsigned long long)(~su)) << 32) | (unsigned)i;
    }
    __syncthreads();
    for (int k = 2; k <= NPER; k <<= 1) {
        for (int j = k >> 1; j > 0; j >>= 1) {
            for (int i = t; i < NPER; i += blockDim.x) {
                int ixj = i ^ j;
                if (ixj > i) {
                    unsigned long long a = keys[i], c = keys[ixj];
                    bool up = ((i & k) == 0);
                    if ((a > c) == up) { keys[i] = c; keys[ixj] = a; }
                }
            }
            __syncthreads();
        }
    }
    for (int i = t; i < NPER; i += blockDim.x) {
        int local = (int)(keys[i] & 0xFFFFFFFFull);
        int node  = b * NPER + local;
        if (i < KSEL) {
            int p = b * KSEL + i;
            g_perm[p] = node;
            g_newidx[node] = p;
        } else {
            g_newidx[node] = -1;
        }
    }
}

// Parallel partial sums: 64 blocks x 256 threads, each thread 4 bins (uint4).
__global__ void k_sum(int pass) {
    const uint4* hist4 = (const uint4*)(pass ? g_h2 : g_h1);
    __shared__ unsigned sh[8];
    int t = threadIdx.x;
    uint4 v = hist4[blockIdx.x * 256 + t];
    unsigned s = v.x + v.y + v.z + v.w;
#pragma unroll
    for (int o = 16; o; o >>= 1) s += __shfl_xor_sync(0xFFFFFFFFu, s, o);
    if ((t & 31) == 0) sh[t >> 5] = s;
    __syncthreads();
    if (t < 8) {
        s = sh[t];
#pragma unroll
        for (int o = 4; o; o >>= 1) s += __shfl_xor_sync(0xFFu, s, o, 8);
        if (t == 0) g_psum[blockIdx.x] = s;
    }
}

// One block: psums staged via SMEM, then 1024 threads shuffle-scan the
// winning 1024-bin chunk.
__global__ void k_find(int pass) {
    __shared__ unsigned warpsum[32];
    __shared__ unsigned spsum[64];
    __shared__ unsigned s_excl;
    __shared__ int s_blk;
    const unsigned* hist = pass ? g_h2 : g_h1;
    int t = threadIdx.x;
    unsigned target = pass ? g_rank2 : (unsigned)RANK_ASC;
    if (t < 64) spsum[t] = g_psum[t];
    __syncthreads();
    if (t == 0) {
        unsigned cum = 0;
        int B = 0;
        for (int i = 0; i < 64; i++) {
            unsigned p = spsum[i];
            if (target < cum + p) { B = i; break; }
            cum += p;
        }
        s_excl = cum; s_blk = B;
    }
    __syncthreads();
    int B = s_blk;
    unsigned h = hist[B * 1024 + t];
    unsigned inc = h;
#pragma unroll
    for (int o = 1; o < 32; o <<= 1) {
        unsigned n = __shfl_up_sync(0xFFFFFFFFu, inc, o);
        if ((t & 31) >= o) inc += n;
    }
    if ((t & 31) == 31) warpsum[t >> 5] = inc;
    __syncthreads();
    if (t < 32) {
        unsigned w = warpsum[t];
#pragma unroll
        for (int o = 1; o < 32; o <<= 1) {
            unsigned n = __shfl_up_sync(0xFFFFFFFFu, w, o);
            if (t >= o) w += n;
        }
        warpsum[t] = w;
    }
    __syncthreads();
    unsigned incl = inc + ((t >= 32) ? warpsum[(t >> 5) - 1] : 0u);
    unsigned excl = s_excl + incl - h;
    if (target >= excl && target < excl + h) {
        unsigned bin = (unsigned)(B * 1024 + t);
        if (pass == 0) { g_binT = bin; g_rank2 = target - excl; }
        else           { g_uth = (g_binT << 16) | bin; }
    }
}

// Pass-2 histogram; threads 0-16383 also re-zero g_h1 for the next replay.
__global__ void k_hist2() {
    int e = blockIdx.x * blockDim.x + threadIdx.x;
    if (e < 16384) ((uint4*)g_h1)[e] = make_uint4(0, 0, 0, 0);
    unsigned u = g_Su[e];
    if ((u >> 16) == g_binT) atomicAdd(&g_h2[u & 0xFFFFu], 1u);
}

// Streaming edge outputs: 2 threads/edge (indices, masked attrs, select).
// Threads 0..16383 also re-zero g_h2 for the next replay.
__global__ void k_edges(const int* __restrict__ ei, const float4* __restrict__ attr4,
                        float* __restrict__ out) {
    int h = blockIdx.x * blockDim.x + threadIdx.x;   // EE*2 threads
    if (h < 16384) ((uint4*)g_h2)[h] = make_uint4(0, 0, 0, 0);
    int e = h >> 1, half = h & 1;
    int r = ei[e], c = ei[EE + e];
    int nr = g_newidx[r], nc = g_newidx[c];
    bool valid = (nr >= 0) && (nc >= 0);
    if (half == 0) {
        out[O1 + e] = valid ? (float)nr : -1.0f;
    } else {
        out[O1 + EE + e] = valid ? (float)nc : -1.0f;
        out[O4 + e] = (g_Su[e] > g_uth) ? 1.0f : 0.0f;
    }
    float4 av = valid ? attr4[e * 2 + half] : make_float4(0, 0, 0, 0);
    ((float4*)(out + O2))[e * 2 + half] = av;
}

// x_out gather (16 threads/row, exact fp32) + batch_out.
__global__ void k_final(const float4* __restrict__ xv, float* __restrict__ out) {
    int t = blockIdx.x * blockDim.x + threadIdx.x;
    if (t < PTOT) out[O3 + t] = (float)(t / KSEL);
    if (t < PTOT * 16) {
        int p = t >> 4, j = t & 15;
        int node = g_perm[p];
        ((float4*)out)[p * 16 + j] = xv[(size_t)node * 16 + j];
    }
}

extern "C" void kernel_launch(void* const* d_in, const int* in_sizes, int n_in,
                              void* d_out, int out_size) {
    const float* x    = (const float*)d_in[0];
    const float* xs   = (const float*)d_in[1];
    const int*   ei   = (const int*)d_in[2];
    const float* attr = (const float*)d_in[3];
    float* out = (float*)d_out;

    k_ehist<<<EE / EPB, 256>>>(ei);                // #1
    k_bscan<<<1, 1024>>>();                        // #2
    k_escatter<<<EE / EPB, 256>>>(ei);             // #3
    k_S2<<<NBKT, 256>>>((const float4*)x);         // #4 (ncu capture slot)
    k_topk<<<NB, 1024>>>(xs);                      // #5
    k_sum<<<64, 256>>>(0);                         // #6
    k_find<<<1, 1024>>>(0);                        // #7
    k_hist2<<<EE / 256, 256>>>();                  // #8
    k_sum<<<64, 256>>>(1);                         // #9
    k_find<<<1, 1024>>>(1);                        // #10
    k_edges<<<EE * 2 / 256, 256>>>(ei, (const float4*)attr, out);  // #11
    k_final<<<PTOT * 16 / 256, 256>>>((const float4*)x, out);      // #12
}